// round 3
// baseline (speedup 1.0000x reference)
#include <cuda_runtime.h>
#include <cuda_bf16.h>

// Problem constants (fixed by the reference):
// B=16, T=4096, L=4, H=W=128, D=32, MAX_DIM=0.55
#define NB 16
#define NT 4096
#define NPTS (NB * NT)
#define MAXDIM 0.55f

#define TPB 128            // threads per block
#define PPB 256            // points per block (2 per thread)

// Dynamic shared memory layout (float offsets)
#define OFF_W0   0            // 5*32*32 = 5120, raw layout [i][k][j]
#define OFF_W1   5120         // 5120
#define OFF_B0   10240        // 160
#define OFF_B1   10400        // 160
#define OFF_FP   10560        // 96  fc_p_W [3][32]
#define OFF_FPB  10656        // 32
#define OFF_FO   10688        // 32
#define OFF_FOB  10720        // 1  (pad to 10752)
#define OFF_PW   10752        // 256 slots * 32 (16 int offs + 16 float wts)
#define OFF_CF   (10752+8192) // 256*33 = 8448 (padded cf tile)
#define SMEM_FLOATS (OFF_CF + PPB*33)
#define SMEM_BYTES  (SMEM_FLOATS * 4)

typedef unsigned long long u64;

__device__ __forceinline__ u64 pack2(float lo, float hi) {
    u64 r; asm("mov.b64 %0, {%1,%2};" : "=l"(r) : "f"(lo), "f"(hi)); return r;
}
__device__ __forceinline__ void unpack2(u64 v, float& lo, float& hi) {
    asm("mov.b64 {%0,%1}, %2;" : "=f"(lo), "=f"(hi) : "l"(v));
}
__device__ __forceinline__ u64 fma2(u64 a, u64 b, u64 c) {
    u64 d; asm("fma.rn.f32x2 %0, %1, %2, %3;" : "=l"(d) : "l"(a), "l"(b), "l"(c)); return d;
}

// Per-point projection precompute: fills 16 ints (corner offsets) + 16 floats (weights)
__device__ __forceinline__ void precompute_pw(float* dst, int b,
                                              float qx, float qy, float qz,
                                              const float* __restrict__ C_mat)
{
    const float interval = 2.0f / 127.0f;
#pragma unroll
    for (int l = 0; l < 4; l++) {
        const float* Cm = C_mat + ((b * 4 + l) * 4) * 3;
        float pr0 = Cm[0] * qx + Cm[1] * qy + Cm[2] * qz;
        float pr1 = Cm[3] * qx + Cm[4] * qy + Cm[5] * qz;
        const float denom = Cm[9] + 0.05f;
        pr0 /= denom; pr1 /= denom;
        float xg = (pr0 + 1.0f) / interval;
        float yg = (pr1 + 1.0f) / interval;
        if (xg >= 127.0f) xg = 126.9f;
        if (xg < 0.0f)    xg = 0.0f;
        if (yg >= 127.0f) yg = 126.9f;
        if (yg < 0.0f)    yg = 0.0f;
        const float xl = rintf(xg - 0.5f);
        const float xr = rintf(xg + 0.5f);
        const float yl = rintf(yg - 0.5f);
        const float yh = rintf(yg + 0.5f);
        const int xi_l = (int)xl, xi_r = (int)xr;
        const int yi_l = (int)yl, yi_h = (int)yh;
        const float dx = xr - xg;
        const float dy = yh - yg;
        const int vb = (b * 4 + l) * (128 * 128 * 32);
        ((int4*)dst)[l] = make_int4(vb + (xi_l * 128 + yi_l) * 32,
                                    vb + (xi_r * 128 + yi_l) * 32,
                                    vb + (xi_l * 128 + yi_h) * 32,
                                    vb + (xi_r * 128 + yi_h) * 32);
        ((float4*)(dst + 16))[l] = make_float4(dx * dy,
                                               (1.0f - dx) * dy,
                                               dx * (1.0f - dy),
                                               (1.0f - dx) * (1.0f - dy));
    }
}

__global__ __launch_bounds__(TPB, 2)
void decoder_kernel(const float* __restrict__ p,
                    const float* __restrict__ c,
                    const float* __restrict__ C_mat,
                    const float* __restrict__ fc_p_W,
                    const float* __restrict__ fc_p_b,
                    const float* __restrict__ W0,
                    const float* __restrict__ b0,
                    const float* __restrict__ W1,
                    const float* __restrict__ b1,
                    const float* __restrict__ foW,
                    const float* __restrict__ fob,
                    float* __restrict__ out)
{
    extern __shared__ float sm[];
    const int tid = threadIdx.x;

    // ---- stage all weights (raw layout, j contiguous for f32x2 pairs) ----
    {
        const float4* s0 = (const float4*)W0;
        const float4* s1 = (const float4*)W1;
        float4* d0 = (float4*)(sm + OFF_W0);
        float4* d1 = (float4*)(sm + OFF_W1);
        for (int i = tid; i < 1280; i += TPB) { d0[i] = s0[i]; d1[i] = s1[i]; }
        if (tid < 96)  sm[OFF_FP + tid] = fc_p_W[tid];
        if (tid >= 96 && tid < 96 + 32) {
            int j = tid - 96;
            sm[OFF_FPB + j] = fc_p_b[j];
            sm[OFF_FO + j] = foW[j];
        }
        for (int idx = tid; idx < 160; idx += TPB) {
            sm[OFF_B0 + idx] = b0[idx]; sm[OFF_B1 + idx] = b1[idx];
        }
        if (tid == 0) sm[OFF_FOB] = fob[0];
    }
    __syncthreads();

    const int base  = blockIdx.x * PPB;
    const int b     = base >> 12;     // whole block shares batch index (4096 % 256 == 0)
    const int lane  = tid & 31;
    const int wbase = tid & ~31;      // warp's first thread

    const int gA = base + tid;        // point A: slot tid
    const int gB = base + TPB + tid;  // point B: slot tid + 128

    const float pAx = p[gA * 3 + 0], pAy = p[gA * 3 + 1], pAz = p[gA * 3 + 2];
    const float pBx = p[gB * 3 + 0], pBy = p[gB * 3 + 1], pBz = p[gB * 3 + 2];

    // ---- per-thread precompute for both points ----
    precompute_pw(sm + OFF_PW + tid * 32, b,
                  pAx / MAXDIM, pAy / MAXDIM, pAz / MAXDIM, C_mat);
    precompute_pw(sm + OFF_PW + (TPB + tid) * 32, b,
                  pBx / MAXDIM, pBy / MAXDIM, pBz / MAXDIM, C_mat);
    __syncwarp();

    // ---- warp-cooperative gather: lane = channel, 64 points per warp ----
    // Warp covers slots [wbase, wbase+32) and [128+wbase, 128+wbase+32).
    {
#pragma unroll 1
        for (int half = 0; half < 2; half++) {
            const int slot0 = half * TPB + wbase;
            const float* pwW = sm + OFF_PW + slot0 * 32;
            float*       cfW = sm + OFF_CF + slot0 * 33;
#pragma unroll 2
            for (int t = 0; t < 32; t++) {
                const float* pwt = pwW + t * 32;
                float acc = 0.0f;
#pragma unroll
                for (int l = 0; l < 4; l++) {
                    const int4   o = ((const int4*)pwt)[l];          // broadcast LDS.128
                    const float4 w = ((const float4*)(pwt + 16))[l]; // broadcast LDS.128
                    const float f11 = c[o.x + lane];  // coalesced 128B line
                    const float f12 = c[o.y + lane];
                    const float f21 = c[o.z + lane];
                    const float f22 = c[o.w + lane];
                    acc += w.x * f11 + w.y * f12 + w.z * f21 + w.w * f22;
                }
                cfW[t * 33 + lane] = acc;  // stride 33: conflict-free
            }
        }
    }
    __syncwarp();

    const float* cfA = sm + OFF_CF + tid * 33;
    const float* cfB = sm + OFF_CF + (TPB + tid) * 33;

    // ---- net = fc_p(p) for both points ----
    float netA[32], netB[32];
#pragma unroll
    for (int j = 0; j < 32; j++) {
        const float w0j = sm[OFF_FP + j];
        const float w1j = sm[OFF_FP + 32 + j];
        const float w2j = sm[OFF_FP + 64 + j];
        const float bj  = sm[OFF_FPB + j];
        netA[j] = bj + pAx * w0j + pAy * w1j + pAz * w2j;
        netB[j] = bj + pBx * w0j + pBy * w1j + pBz * w2j;
    }

    // ---- 5 ResnetBlockFC blocks: weights loaded once, used for both points ----
#pragma unroll 1
    for (int i = 0; i < 5; i++) {
        const float* Wr0 = sm + OFF_W0 + i * 1024;
        const float* Wr1 = sm + OFF_W1 + i * 1024;

#pragma unroll
        for (int j = 0; j < 32; j++) { netA[j] += cfA[j]; netB[j] += cfB[j]; }

        // fc_0
        u64 aA[16], aB[16];
        {
            const ulonglong2* bp = (const ulonglong2*)(sm + OFF_B0 + i * 32);
#pragma unroll
            for (int q = 0; q < 8; q++) {
                ulonglong2 v = bp[q];
                aA[2*q] = v.x; aA[2*q+1] = v.y;
                aB[2*q] = v.x; aB[2*q+1] = v.y;
            }
        }
#pragma unroll 8
        for (int k = 0; k < 32; k++) {
            const float rA = fmaxf(netA[k], 0.0f);
            const float rB = fmaxf(netB[k], 0.0f);
            const u64 rA2 = pack2(rA, rA);
            const u64 rB2 = pack2(rB, rB);
            const ulonglong2* wr = (const ulonglong2*)(Wr0 + k * 32);
#pragma unroll
            for (int q = 0; q < 8; q++) {
                ulonglong2 w = wr[q];
                aA[2*q]   = fma2(rA2, w.x, aA[2*q]);
                aA[2*q+1] = fma2(rA2, w.y, aA[2*q+1]);
                aB[2*q]   = fma2(rB2, w.x, aB[2*q]);
                aB[2*q+1] = fma2(rB2, w.y, aB[2*q+1]);
            }
        }
        // h = relu(fc_0 out)
        float hA[32], hB[32];
#pragma unroll
        for (int q = 0; q < 16; q++) {
            float lo, hi;
            unpack2(aA[q], lo, hi); hA[2*q] = fmaxf(lo, 0.0f); hA[2*q+1] = fmaxf(hi, 0.0f);
            unpack2(aB[q], lo, hi); hB[2*q] = fmaxf(lo, 0.0f); hB[2*q+1] = fmaxf(hi, 0.0f);
        }
        // fc_1
        u64 cA[16], cB[16];
        {
            const ulonglong2* bp = (const ulonglong2*)(sm + OFF_B1 + i * 32);
#pragma unroll
            for (int q = 0; q < 8; q++) {
                ulonglong2 v = bp[q];
                cA[2*q] = v.x; cA[2*q+1] = v.y;
                cB[2*q] = v.x; cB[2*q+1] = v.y;
            }
        }
#pragma unroll 8
        for (int k = 0; k < 32; k++) {
            const u64 rA2 = pack2(hA[k], hA[k]);
            const u64 rB2 = pack2(hB[k], hB[k]);
            const ulonglong2* wr = (const ulonglong2*)(Wr1 + k * 32);
#pragma unroll
            for (int q = 0; q < 8; q++) {
                ulonglong2 w = wr[q];
                cA[2*q]   = fma2(rA2, w.x, cA[2*q]);
                cA[2*q+1] = fma2(rA2, w.y, cA[2*q+1]);
                cB[2*q]   = fma2(rB2, w.x, cB[2*q]);
                cB[2*q+1] = fma2(rB2, w.y, cB[2*q+1]);
            }
        }
        // residual add
#pragma unroll
        for (int q = 0; q < 16; q++) {
            float lo, hi;
            unpack2(cA[q], lo, hi); netA[2*q] += lo; netA[2*q+1] += hi;
            unpack2(cB[q], lo, hi); netB[2*q] += lo; netB[2*q+1] += hi;
        }
    }

    // ---- out = relu(net) @ fc_out_W + fc_out_b ----
    float oA = sm[OFF_FOB], oB = sm[OFF_FOB];
#pragma unroll
    for (int k = 0; k < 32; k++) {
        const float w = sm[OFF_FO + k];
        oA += fmaxf(netA[k], 0.0f) * w;
        oB += fmaxf(netB[k], 0.0f) * w;
    }
    out[gA] = oA;
    out[gB] = oB;
}

extern "C" void kernel_launch(void* const* d_in, const int* in_sizes, int n_in,
                              void* d_out, int out_size) {
    // metadata order:
    // 0:p 1:z 2:c 3:C_mat 4:fc_p_W 5:fc_p_b 6:blocks_W0 7:blocks_b0
    // 8:blocks_W1 9:blocks_b1 10:fc_out_W 11:fc_out_b   (z unused by reference)
    const float* p      = (const float*)d_in[0];
    const float* c      = (const float*)d_in[2];
    const float* C_mat  = (const float*)d_in[3];
    const float* fc_p_W = (const float*)d_in[4];
    const float* fc_p_b = (const float*)d_in[5];
    const float* W0     = (const float*)d_in[6];
    const float* b0     = (const float*)d_in[7];
    const float* W1     = (const float*)d_in[8];
    const float* b1     = (const float*)d_in[9];
    const float* foW    = (const float*)d_in[10];
    const float* fob    = (const float*)d_in[11];
    float* out = (float*)d_out;

    cudaFuncSetAttribute(decoder_kernel,
                         cudaFuncAttributeMaxDynamicSharedMemorySize, SMEM_BYTES);

    const int blocks = NPTS / PPB;  // 256
    decoder_kernel<<<blocks, TPB, SMEM_BYTES>>>(p, c, C_mat, fc_p_W, fc_p_b,
                                                W0, b0, W1, b1, foW, fob, out);
}